// round 12
// baseline (speedup 1.0000x reference)
#include <cuda_runtime.h>

// SSIM, fused separable 11x11 Gaussian (sigma=1.5), B=16,C=3,H=W=512, fp32.
// Round-12: attack L1 wall via column reuse. Each thread computes 2 ADJACENT
// output columns; horizontal conv streams 12 float4 taps (LDS.128) applying
// each to both columns (96B/output vs 176B). All-fp32 T = (s,d,s^2,d^2)
// (fp16 proven fatal: C2=9e-4 < fp16 abs err on squares). 64 threads per
// 128x64 tile, single raw buffer + post-transform prefetch, 38KB smem ->
// 6 blocks/SM. Fused finalize via atomic ticket.

constexpr int IMG_H = 512;
constexpr int IMG_W = 512;
constexpr int N_IMG = 48;
constexpr int RAD   = 5;
constexpr int WS    = 11;
constexpr int TW    = 128;            // tile width; 2 cols per thread
constexpr int TH    = 64;
constexpr int LPAD  = 8;
constexpr int COLS  = 144;            // working columns per row
constexpr int RAWW  = 2 * COLS;       // raw row: [a(144) | b(144)]
constexpr int ROWSIN = TH + 2 * RAD;  // 74
constexpr int NGROUP = 7;             // 7*11 = 77 rows swept
constexpr int NTHREADS = 64;
constexpr int F4_PER_ROW   = COLS / 4;          // 36
constexpr int F4_PER_GROUP = F4_PER_ROW * WS;   // 396 (per image)
constexpr int PIX_PER_GROUP = COLS * WS;        // 1584
constexpr int T_ITERS = (PIX_PER_GROUP + NTHREADS - 1) / NTHREADS;  // 25
constexpr int NBLOCKS = (IMG_W / TW) * (IMG_H / TH) * N_IMG;        // 1536

constexpr float C1f = 0.01f * 0.01f;
constexpr float C2f = 0.03f * 0.03f;

__device__ constexpr float GW[WS] = {
    0.00102838f, 0.00759876f, 0.03600078f, 0.10936070f, 0.21300554f,
    0.26601173f,
    0.21300554f, 0.10936070f, 0.03600078f, 0.00759876f, 0.00102838f
};

__device__ double   g_accum;
__device__ unsigned g_done;

__device__ __forceinline__ void cpa16(void* smem_dst, const void* gmem_src, bool pred)
{
    unsigned s = (unsigned)__cvta_generic_to_shared(smem_dst);
    int n = pred ? 16 : 0;   // src-size 0 -> 16B zero-fill
    asm volatile("cp.async.cg.shared.global [%0], [%1], 16, %2;\n"
                 :: "r"(s), "l"(gmem_src), "r"(n));
}

__device__ __forceinline__ void issue_group(
    int g, int t, int x0, int y0,
    const float* __restrict__ p1, const float* __restrict__ p2,
    float (*raw)[RAWW])
{
    #pragma unroll
    for (int q = t; q < F4_PER_GROUP; q += NTHREADS) {
        const int r   = q / F4_PER_ROW;
        const int c4  = q - r * F4_PER_ROW;
        const int y   = y0 - RAD + g * WS + r;
        const int col = x0 - LPAD + c4 * 4;
        const bool ok = ((unsigned)y < (unsigned)IMG_H) &&
                        ((unsigned)col <= (unsigned)(IMG_W - 4));
        const long off = (long)y * IMG_W + col;
        cpa16(&raw[r][c4 * 4],        p1 + off, ok);
        cpa16(&raw[r][COLS + c4 * 4], p2 + off, ok);
    }
}

__global__ void __launch_bounds__(NTHREADS, 6)
ssim_main_kernel(const float* __restrict__ img1, const float* __restrict__ img2,
                 float* __restrict__ out)
{
    __shared__ __align__(16) float  raw[WS][RAWW];   // single-buffered a|b
    __shared__ __align__(16) float4 T[WS][COLS];     // (s, d, s^2, d^2)
    __shared__ float warp_sums[NTHREADS / 32];

    const int t  = threadIdx.x;
    const int x0 = blockIdx.x * TW;
    const int y0 = blockIdx.y * TH;
    const long imgOff = (long)blockIdx.z * (long)(IMG_H * IMG_W);
    const float* __restrict__ p1 = img1 + imgOff;
    const float* __restrict__ p2 = img2 + imgOff;

    issue_group(0, t, x0, y0, p1, p2, raw);
    asm volatile("cp.async.commit_group;\n");

    // ring[ph][m]: m = {s0,s1,d0,d1,ss0,ss1,dd0,dd1} for the 2 columns
    float ring[WS][8];
    float acc = 0.0f;

    for (int g = 0; g < NGROUP; ++g) {
        asm volatile("cp.async.wait_group 0;\n" ::: "memory");
        __syncthreads();                 // raw rows landed; prev compute done

        // ---- transform: (a,b) -> float4(s, d, s*s, d*d), once per pixel ----
        #pragma unroll
        for (int it = 0; it < T_ITERS; ++it) {
            const int u = t + it * NTHREADS;
            if (u < PIX_PER_GROUP) {
                const int r = u / COLS;
                const int c = u - r * COLS;
                const float a = raw[r][c];
                const float b = raw[r][COLS + c];
                const float s = a + b;
                const float d = a - b;
                T[r][c] = make_float4(s, d, s * s, d * d);
            }
        }
        __syncthreads();                 // T visible; raw free for refill

        if (g + 1 < NGROUP)
            issue_group(g + 1, t, x0, y0, p1, p2, raw);
        asm volatile("cp.async.commit_group;\n");

        #pragma unroll
        for (int ph = 0; ph < WS; ++ph) {
            const int ir = g * WS + ph;
            if (ir < ROWSIN) {
                // out0 = col 2t (window T[2t+3..2t+13]),
                // out1 = col 2t+1 (window T[2t+4..2t+14]) -> 12 streamed taps
                const float4* __restrict__ rw = &T[ph][2 * t + 3];

                float h0s = 0.f, h0d = 0.f, h0ss = 0.f, h0dd = 0.f;
                float h1s = 0.f, h1d = 0.f, h1ss = 0.f, h1dd = 0.f;
                #pragma unroll
                for (int j = 0; j < 12; ++j) {
                    const float4 v = rw[j];      // one LDS.128, used twice
                    if (j <= 10) {
                        const float w = GW[j];
                        h0s  = fmaf(w, v.x, h0s);
                        h0d  = fmaf(w, v.y, h0d);
                        h0ss = fmaf(w, v.z, h0ss);
                        h0dd = fmaf(w, v.w, h0dd);
                    }
                    if (j >= 1) {
                        const float w = GW[j - 1];
                        h1s  = fmaf(w, v.x, h1s);
                        h1d  = fmaf(w, v.y, h1d);
                        h1ss = fmaf(w, v.z, h1ss);
                        h1dd = fmaf(w, v.w, h1dd);
                    }
                }
                ring[ph][0] = h0s;  ring[ph][1] = h1s;
                ring[ph][2] = h0d;  ring[ph][3] = h1d;
                ring[ph][4] = h0ss; ring[ph][5] = h1ss;
                ring[ph][6] = h0dd; ring[ph][7] = h1dd;

                // -- vertical conv from register ring + SSIM, both columns --
                if (ir >= WS - 1) {
                    float m0a = 0.f, m0b = 0.f, m1a = 0.f, m1b = 0.f;
                    float m2a = 0.f, m2b = 0.f, m3a = 0.f, m3b = 0.f;
                    #pragma unroll
                    for (int k = 0; k < WS; ++k) {
                        const int s = (ph + 1 + k) % WS;
                        const float w = GW[k];
                        m0a = fmaf(w, ring[s][0], m0a);
                        m0b = fmaf(w, ring[s][1], m0b);
                        m1a = fmaf(w, ring[s][2], m1a);
                        m1b = fmaf(w, ring[s][3], m1b);
                        m2a = fmaf(w, ring[s][4], m2a);
                        m2b = fmaf(w, ring[s][5], m2b);
                        m3a = fmaf(w, ring[s][6], m3a);
                        m3b = fmaf(w, ring[s][7], m3b);
                    }
                    {
                        const float P  = m0a * m0a;
                        const float Q  = m1a * m1a;
                        const float SP = P + Q, SM = P - Q;
                        const float ES = m2a + m3a, ED = m2a - m3a;
                        const float n1 = fmaf(SM, 0.5f, C1f);
                        const float n2 = fmaf(ED - SM, 0.5f, C2f);
                        const float d1 = fmaf(SP, 0.5f, C1f);
                        const float d2 = fmaf(ES - SP, 0.5f, C2f);
                        acc += __fdividef(n1 * n2, d1 * d2);
                    }
                    {
                        const float P  = m0b * m0b;
                        const float Q  = m1b * m1b;
                        const float SP = P + Q, SM = P - Q;
                        const float ES = m2b + m3b, ED = m2b - m3b;
                        const float n1 = fmaf(SM, 0.5f, C1f);
                        const float n2 = fmaf(ED - SM, 0.5f, C2f);
                        const float d1 = fmaf(SP, 0.5f, C1f);
                        const float d2 = fmaf(ES - SP, 0.5f, C2f);
                        acc += __fdividef(n1 * n2, d1 * d2);
                    }
                }
            }
        }

        __syncthreads();                 // compute done; T/raw may be reused
    }

    // ---- block reduction ----
    #pragma unroll
    for (int o = 16; o > 0; o >>= 1)
        acc += __shfl_down_sync(0xffffffffu, acc, o);
    if ((t & 31) == 0) warp_sums[t >> 5] = acc;
    __syncthreads();

    if (t == 0) {
        float bs = 0.0f;
        #pragma unroll
        for (int w = 0; w < NTHREADS / 32; ++w) bs += warp_sums[w];
        atomicAdd(&g_accum, (double)bs);
        __threadfence();
        const unsigned ticket = atomicAdd(&g_done, 1u);
        if (ticket == NBLOCKS - 1) {
            __threadfence();
            out[0] = (float)(g_accum *
                     (1.0 / ((double)N_IMG * (double)IMG_H * (double)IMG_W)));
            g_accum = 0.0;
            g_done  = 0u;
        }
    }
}

extern "C" void kernel_launch(void* const* d_in, const int* in_sizes, int n_in,
                              void* d_out, int out_size)
{
    const float* img1 = (const float*)d_in[0];
    const float* img2 = (const float*)d_in[1];
    float* out = (float*)d_out;

    dim3 grid(IMG_W / TW, IMG_H / TH, N_IMG);   // 4 x 8 x 48 = 1536 blocks
    ssim_main_kernel<<<grid, NTHREADS>>>(img1, img2, out);
}

// round 13
// speedup vs baseline: 1.1663x; 1.1663x over previous
#include <cuda_runtime.h>

// SSIM, fused separable 11x11 Gaussian (sigma=1.5), B=16,C=3,H=W=512, fp32.
// Round-13: R9 compute core (1 col/thread, 11 LDS.128 + 44 FFMA-imm/phase,
// scalar ring) + single raw buffer with post-transform prefetch (smem 51->38KB)
// + launch_bounds(128,5) -> 20 warps/SM to saturate the L1 crossbar.
// All-fp32 maps (fp16 proven fatal: C2=9e-4 < fp16 abs err on squares).
// Fused finalize via atomic ticket.

constexpr int IMG_H = 512;
constexpr int IMG_W = 512;
constexpr int N_IMG = 48;
constexpr int RAD   = 5;
constexpr int WS    = 11;
constexpr int TW    = 128;
constexpr int TH    = 64;
constexpr int LPAD  = 8;
constexpr int COLS  = 144;            // working columns per row
constexpr int RAWW  = 2 * COLS;       // raw row: [a(144) | b(144)]
constexpr int ROWSIN = TH + 2 * RAD;  // 74
constexpr int NGROUP = 7;             // 7*11 = 77 rows swept
constexpr int NTHREADS = 128;
constexpr int F4_PER_ROW   = COLS / 4;          // 36
constexpr int F4_PER_GROUP = F4_PER_ROW * WS;   // 396 (per image)
constexpr int PIX_PER_GROUP = COLS * WS;        // 1584
constexpr int T_ITERS = (PIX_PER_GROUP + NTHREADS - 1) / NTHREADS;  // 13
constexpr int NBLOCKS = (IMG_W / TW) * (IMG_H / TH) * N_IMG;        // 1536

constexpr float C1f = 0.01f * 0.01f;
constexpr float C2f = 0.03f * 0.03f;

__device__ constexpr float GW[WS] = {
    0.00102838f, 0.00759876f, 0.03600078f, 0.10936070f, 0.21300554f,
    0.26601173f,
    0.21300554f, 0.10936070f, 0.03600078f, 0.00759876f, 0.00102838f
};

__device__ double   g_accum;
__device__ unsigned g_done;

__device__ __forceinline__ void cpa16(void* smem_dst, const void* gmem_src, bool pred)
{
    unsigned s = (unsigned)__cvta_generic_to_shared(smem_dst);
    int n = pred ? 16 : 0;   // src-size 0 -> 16B zero-fill
    asm volatile("cp.async.cg.shared.global [%0], [%1], 16, %2;\n"
                 :: "r"(s), "l"(gmem_src), "r"(n));
}

__device__ __forceinline__ void issue_group(
    int g, int t, int x0, int y0,
    const float* __restrict__ p1, const float* __restrict__ p2,
    float (*raw)[RAWW])
{
    #pragma unroll
    for (int q = t; q < F4_PER_GROUP; q += NTHREADS) {
        const int r   = q / F4_PER_ROW;
        const int c4  = q - r * F4_PER_ROW;
        const int y   = y0 - RAD + g * WS + r;
        const int col = x0 - LPAD + c4 * 4;
        const bool ok = ((unsigned)y < (unsigned)IMG_H) &&
                        ((unsigned)col <= (unsigned)(IMG_W - 4));
        const long off = (long)y * IMG_W + col;
        cpa16(&raw[r][c4 * 4],        p1 + off, ok);
        cpa16(&raw[r][COLS + c4 * 4], p2 + off, ok);
    }
}

__global__ void __launch_bounds__(NTHREADS, 5)
ssim_main_kernel(const float* __restrict__ img1, const float* __restrict__ img2,
                 float* __restrict__ out)
{
    __shared__ __align__(16) float  raw[WS][RAWW];   // single-buffered a|b
    __shared__ __align__(16) float4 T[WS][COLS];     // (s, d, s^2, d^2)
    __shared__ float warp_sums[NTHREADS / 32];

    const int t  = threadIdx.x;
    const int x0 = blockIdx.x * TW;
    const int y0 = blockIdx.y * TH;
    const long imgOff = (long)blockIdx.z * (long)(IMG_H * IMG_W);
    const float* __restrict__ p1 = img1 + imgOff;
    const float* __restrict__ p2 = img2 + imgOff;

    issue_group(0, t, x0, y0, p1, p2, raw);
    asm volatile("cp.async.commit_group;\n");

    float ring[WS][4];     // horizontal conv results: G*s, G*d, G*s^2, G*d^2
    float acc = 0.0f;

    for (int g = 0; g < NGROUP; ++g) {
        asm volatile("cp.async.wait_group 0;\n" ::: "memory");
        __syncthreads();                 // raw rows landed; prev compute done

        // ---- transform: (a,b) -> float4(s, d, s*s, d*d), once per pixel ----
        #pragma unroll
        for (int it = 0; it < T_ITERS; ++it) {
            const int u = t + it * NTHREADS;
            if (u < PIX_PER_GROUP) {
                const int r = u / COLS;
                const int c = u - r * COLS;
                const float a = raw[r][c];
                const float b = raw[r][COLS + c];
                const float s = a + b;
                const float d = a - b;
                T[r][c] = make_float4(s, d, s * s, d * d);
            }
        }
        __syncthreads();                 // T visible; raw free for refill

        if (g + 1 < NGROUP)
            issue_group(g + 1, t, x0, y0, p1, p2, raw);
        asm volatile("cp.async.commit_group;\n");

        #pragma unroll
        for (int ph = 0; ph < WS; ++ph) {
            const int ir = g * WS + ph;
            if (ir < ROWSIN) {
                const float4* __restrict__ rw = &T[ph][t + 3];

                // -- horizontal 11-tap conv of 4 maps: 11 LDS.128 + 44 FFMA --
                float h0 = 0.f, h1 = 0.f, h2 = 0.f, h3 = 0.f;
                #pragma unroll
                for (int k = 0; k < WS; ++k) {
                    const float4 v = rw[k];
                    const float  w = GW[k];
                    h0 = fmaf(w, v.x, h0);
                    h1 = fmaf(w, v.y, h1);
                    h2 = fmaf(w, v.z, h2);
                    h3 = fmaf(w, v.w, h3);
                }
                ring[ph][0] = h0; ring[ph][1] = h1;
                ring[ph][2] = h2; ring[ph][3] = h3;

                // -- vertical 11-tap conv from register ring + SSIM --
                if (ir >= WS - 1) {
                    float m0 = 0.f, m1 = 0.f, m2 = 0.f, m3 = 0.f;
                    #pragma unroll
                    for (int k = 0; k < WS; ++k) {
                        const int s = (ph + 1 + k) % WS;
                        const float w = GW[k];
                        m0 = fmaf(w, ring[s][0], m0);
                        m1 = fmaf(w, ring[s][1], m1);
                        m2 = fmaf(w, ring[s][2], m2);
                        m3 = fmaf(w, ring[s][3], m3);
                    }
                    const float P  = m0 * m0;            // (G*s)^2
                    const float Q  = m1 * m1;            // (G*d)^2
                    const float SP = P + Q;              // 2(mu1^2+mu2^2)
                    const float SM = P - Q;              // 4 mu1 mu2
                    const float ES = m2 + m3;            // 2 E[x1^2+x2^2]
                    const float ED = m2 - m3;            // 4 E[x1 x2]
                    const float n1 = fmaf(SM, 0.5f, C1f);        // 2mu1mu2+C1
                    const float n2 = fmaf(ED - SM, 0.5f, C2f);   // 2sig12+C2
                    const float d1 = fmaf(SP, 0.5f, C1f);        // mu^2 sum+C1
                    const float d2 = fmaf(ES - SP, 0.5f, C2f);   // sig sum+C2
                    acc += __fdividef(n1 * n2, d1 * d2);
                }
            }
        }

        __syncthreads();                 // compute done; T/raw may be reused
    }

    // ---- block reduction ----
    #pragma unroll
    for (int o = 16; o > 0; o >>= 1)
        acc += __shfl_down_sync(0xffffffffu, acc, o);
    if ((t & 31) == 0) warp_sums[t >> 5] = acc;
    __syncthreads();

    if (t == 0) {
        float bs = 0.0f;
        #pragma unroll
        for (int w = 0; w < NTHREADS / 32; ++w) bs += warp_sums[w];
        atomicAdd(&g_accum, (double)bs);
        __threadfence();
        const unsigned ticket = atomicAdd(&g_done, 1u);
        if (ticket == NBLOCKS - 1) {
            __threadfence();
            out[0] = (float)(g_accum *
                     (1.0 / ((double)N_IMG * (double)IMG_H * (double)IMG_W)));
            g_accum = 0.0;
            g_done  = 0u;
        }
    }
}

extern "C" void kernel_launch(void* const* d_in, const int* in_sizes, int n_in,
                              void* d_out, int out_size)
{
    const float* img1 = (const float*)d_in[0];
    const float* img2 = (const float*)d_in[1];
    float* out = (float*)d_out;

    dim3 grid(IMG_W / TW, IMG_H / TH, N_IMG);   // 4 x 8 x 48 = 1536 blocks
    ssim_main_kernel<<<grid, NTHREADS>>>(img1, img2, out);
}

// round 17
// speedup vs baseline: 1.5560x; 1.3342x over previous
#include <cuda_runtime.h>

// SSIM, fused separable 11x11 Gaussian (sigma=1.5), B=16,C=3,H=W=512, fp32.
// Round-14: balance L1 vs issue. Transform stores float2 (s,d) only (8B/col);
// horizontal conv: 1 LDS.64 + 2 FMUL (squares in registers) + 4 FFMA per tap
// -> 22 L1 wavefronts/phase (was 44 with float4 T) at +22 FMUL issue.
// All-fp32 (fp16 proven fatal: C2=9e-4 < fp16 abs err on squares).
// 128 threads per 128x64 tile, single raw buffer + post-transform prefetch,
// launch_bounds(128,5), scalar ring, fused finalize via atomic ticket.

constexpr int IMG_H = 512;
constexpr int IMG_W = 512;
constexpr int N_IMG = 48;
constexpr int RAD   = 5;
constexpr int WS    = 11;
constexpr int TW    = 128;
constexpr int TH    = 64;
constexpr int LPAD  = 8;
constexpr int COLS  = 144;            // working columns per row
constexpr int RAWW  = 2 * COLS;       // raw row: [a(144) | b(144)]
constexpr int ROWSIN = TH + 2 * RAD;  // 74
constexpr int NGROUP = 7;             // 7*11 = 77 rows swept
constexpr int NTHREADS = 128;
constexpr int F4_PER_ROW   = COLS / 4;          // 36
constexpr int F4_PER_GROUP = F4_PER_ROW * WS;   // 396 (per image)
constexpr int PIX_PER_GROUP = COLS * WS;        // 1584
constexpr int T_ITERS = (PIX_PER_GROUP + NTHREADS - 1) / NTHREADS;  // 13
constexpr int NBLOCKS = (IMG_W / TW) * (IMG_H / TH) * N_IMG;        // 1536

constexpr float C1f = 0.01f * 0.01f;
constexpr float C2f = 0.03f * 0.03f;

__device__ constexpr float GW[WS] = {
    0.00102838f, 0.00759876f, 0.03600078f, 0.10936070f, 0.21300554f,
    0.26601173f,
    0.21300554f, 0.10936070f, 0.03600078f, 0.00759876f, 0.00102838f
};

__device__ double   g_accum;
__device__ unsigned g_done;

__device__ __forceinline__ void cpa16(void* smem_dst, const void* gmem_src, bool pred)
{
    unsigned s = (unsigned)__cvta_generic_to_shared(smem_dst);
    int n = pred ? 16 : 0;   // src-size 0 -> 16B zero-fill
    asm volatile("cp.async.cg.shared.global [%0], [%1], 16, %2;\n"
                 :: "r"(s), "l"(gmem_src), "r"(n));
}

__device__ __forceinline__ void issue_group(
    int g, int t, int x0, int y0,
    const float* __restrict__ p1, const float* __restrict__ p2,
    float (*raw)[RAWW])
{
    #pragma unroll
    for (int q = t; q < F4_PER_GROUP; q += NTHREADS) {
        const int r   = q / F4_PER_ROW;
        const int c4  = q - r * F4_PER_ROW;
        const int y   = y0 - RAD + g * WS + r;
        const int col = x0 - LPAD + c4 * 4;
        const bool ok = ((unsigned)y < (unsigned)IMG_H) &&
                        ((unsigned)col <= (unsigned)(IMG_W - 4));
        const long off = (long)y * IMG_W + col;
        cpa16(&raw[r][c4 * 4],        p1 + off, ok);
        cpa16(&raw[r][COLS + c4 * 4], p2 + off, ok);
    }
}

__global__ void __launch_bounds__(NTHREADS, 5)
ssim_main_kernel(const float* __restrict__ img1, const float* __restrict__ img2,
                 float* __restrict__ out)
{
    __shared__ __align__(16) float  raw[WS][RAWW];   // single-buffered a|b
    __shared__ __align__(8)  float2 SD[WS][COLS];    // (s, d) per column
    __shared__ float warp_sums[NTHREADS / 32];

    const int t  = threadIdx.x;
    const int x0 = blockIdx.x * TW;
    const int y0 = blockIdx.y * TH;
    const long imgOff = (long)blockIdx.z * (long)(IMG_H * IMG_W);
    const float* __restrict__ p1 = img1 + imgOff;
    const float* __restrict__ p2 = img2 + imgOff;

    issue_group(0, t, x0, y0, p1, p2, raw);
    asm volatile("cp.async.commit_group;\n");

    float ring[WS][4];     // horizontal conv results: G*s, G*d, G*s^2, G*d^2
    float acc = 0.0f;

    for (int g = 0; g < NGROUP; ++g) {
        asm volatile("cp.async.wait_group 0;\n" ::: "memory");
        __syncthreads();                 // raw rows landed; prev compute done

        // ---- transform: (a,b) -> float2(s, d), once per pixel ----
        #pragma unroll
        for (int it = 0; it < T_ITERS; ++it) {
            const int u = t + it * NTHREADS;
            if (u < PIX_PER_GROUP) {
                const int r = u / COLS;
                const int c = u - r * COLS;
                const float a = raw[r][c];
                const float b = raw[r][COLS + c];
                SD[r][c] = make_float2(a + b, a - b);
            }
        }
        __syncthreads();                 // SD visible; raw free for refill

        if (g + 1 < NGROUP)
            issue_group(g + 1, t, x0, y0, p1, p2, raw);
        asm volatile("cp.async.commit_group;\n");

        #pragma unroll
        for (int ph = 0; ph < WS; ++ph) {
            const int ir = g * WS + ph;
            if (ir < ROWSIN) {
                const float2* __restrict__ rw = &SD[ph][t + 3];

                // -- horizontal 11-tap conv: 1 LDS.64 + 2 FMUL + 4 FFMA/tap --
                float h0 = 0.f, h1 = 0.f, h2 = 0.f, h3 = 0.f;
                #pragma unroll
                for (int k = 0; k < WS; ++k) {
                    const float2 v = rw[k];
                    const float  w = GW[k];
                    h0 = fmaf(w, v.x,       h0);
                    h1 = fmaf(w, v.y,       h1);
                    h2 = fmaf(w, v.x * v.x, h2);
                    h3 = fmaf(w, v.y * v.y, h3);
                }
                ring[ph][0] = h0; ring[ph][1] = h1;
                ring[ph][2] = h2; ring[ph][3] = h3;

                // -- vertical 11-tap conv from register ring + SSIM --
                if (ir >= WS - 1) {
                    float m0 = 0.f, m1 = 0.f, m2 = 0.f, m3 = 0.f;
                    #pragma unroll
                    for (int k = 0; k < WS; ++k) {
                        const int s = (ph + 1 + k) % WS;
                        const float w = GW[k];
                        m0 = fmaf(w, ring[s][0], m0);
                        m1 = fmaf(w, ring[s][1], m1);
                        m2 = fmaf(w, ring[s][2], m2);
                        m3 = fmaf(w, ring[s][3], m3);
                    }
                    const float P  = m0 * m0;            // (G*s)^2
                    const float Q  = m1 * m1;            // (G*d)^2
                    const float SP = P + Q;              // 2(mu1^2+mu2^2)
                    const float SM = P - Q;              // 4 mu1 mu2
                    const float ES = m2 + m3;            // 2 E[x1^2+x2^2]
                    const float ED = m2 - m3;            // 4 E[x1 x2]
                    const float n1 = fmaf(SM, 0.5f, C1f);        // 2mu1mu2+C1
                    const float n2 = fmaf(ED - SM, 0.5f, C2f);   // 2sig12+C2
                    const float d1 = fmaf(SP, 0.5f, C1f);        // mu^2 sum+C1
                    const float d2 = fmaf(ES - SP, 0.5f, C2f);   // sig sum+C2
                    acc += __fdividef(n1 * n2, d1 * d2);
                }
            }
        }

        __syncthreads();                 // compute done; SD/raw may be reused
    }

    // ---- block reduction ----
    #pragma unroll
    for (int o = 16; o > 0; o >>= 1)
        acc += __shfl_down_sync(0xffffffffu, acc, o);
    if ((t & 31) == 0) warp_sums[t >> 5] = acc;
    __syncthreads();

    if (t == 0) {
        float bs = 0.0f;
        #pragma unroll
        for (int w = 0; w < NTHREADS / 32; ++w) bs += warp_sums[w];
        atomicAdd(&g_accum, (double)bs);
        __threadfence();
        const unsigned ticket = atomicAdd(&g_done, 1u);
        if (ticket == NBLOCKS - 1) {
            __threadfence();
            out[0] = (float)(g_accum *
                     (1.0 / ((double)N_IMG * (double)IMG_H * (double)IMG_W)));
            g_accum = 0.0;
            g_done  = 0u;
        }
    }
}

extern "C" void kernel_launch(void* const* d_in, const int* in_sizes, int n_in,
                              void* d_out, int out_size)
{
    const float* img1 = (const float*)d_in[0];
    const float* img2 = (const float*)d_in[1];
    float* out = (float*)d_out;

    dim3 grid(IMG_W / TW, IMG_H / TH, N_IMG);   // 4 x 8 x 48 = 1536 blocks
    ssim_main_kernel<<<grid, NTHREADS>>>(img1, img2, out);
}